// round 16
// baseline (speedup 1.0000x reference)
#include <cuda_runtime.h>
#include <cuda_bf16.h>
#include <math.h>
#include <stdint.h>

#define HIDDEN 2048
#define BOT    64
#define NEXP   8
#define NTOK   16384

#define BM       64
#define BK       64
#define NTILES   (HIDDEN / BK)       // 32
#define THREADS  256
#define NBLK     (NTOK / BM)         // 256

// ---------------- dynamic smem layout (byte offsets) ---------------------------
#define A_HI(b)   ((b) * 8192)                // 4 bufs: 0..32KB (64 rows x 128B bf16)
#define A_LO(b)   (32768 + (b) * 8192)        // 4 bufs: 32..64KB
#define O_PART    0                           // 16KB k-partials (dead A region post-loop)
#define O_ZB      16384                       // 17408B z buffer [64][68] (dead A region)
#define O_MU      65536                       // 64 f32
#define O_RS      65792
#define O_S       66048
#define O_T       66304
#define O_WUP     66560                       // 2KB raw w_up [8][64]
#define O_LG      68608                       // 2KB logits [64][8]
#define SMEM_TOTAL 70656
#define ZSTRIDE   68

#define SWZ128(off) ((off) ^ (((off) >> 3) & 0x70))

// ---------------- device scratch (no allocations allowed) ----------------------
// B in mma.sync fragment order: index = ((k16blk*8 + n8blk)*32 + lane)*2 + reg
__device__ uint32_t g_Bfh[128 * 8 * 32 * 2];   // 256KB hi fragments
__device__ uint32_t g_Bfl[128 * 8 * 32 * 2];   // 256KB lo fragments
__device__ float g_s[BOT];
__device__ float g_t[BOT];

// ---------------- PTX helpers ---------------------------------------------------
__device__ __forceinline__ uint32_t smem_u32(const void* p) {
    uint32_t a;
    asm("{ .reg .u64 t; cvta.to.shared.u64 t, %1; cvt.u32.u64 %0, t; }" : "=r"(a) : "l"(p));
    return a;
}
#define LDMX4(r, a) \
    asm volatile("ldmatrix.sync.aligned.m8n8.x4.shared.b16 {%0,%1,%2,%3}, [%4];" \
        : "=r"((r)[0]), "=r"((r)[1]), "=r"((r)[2]), "=r"((r)[3]) : "r"(a))

#define MMA16816(d, a, b0, b1) \
    asm volatile("mma.sync.aligned.m16n8k16.row.col.f32.bf16.bf16.f32 " \
        "{%0,%1,%2,%3}, {%4,%5,%6,%7}, {%8,%9}, {%0,%1,%2,%3};" \
        : "+f"((d)[0]), "+f"((d)[1]), "+f"((d)[2]), "+f"((d)[3]) \
        : "r"((a)[0]), "r"((a)[1]), "r"((a)[2]), "r"((a)[3]), "r"(b0), "r"(b1))

// ---------------- prep: G = gamma*W -> bf16 hi/lo in FRAGMENT order -------------
__global__ void prep_kernel(const float* __restrict__ w_down,
                            const float* __restrict__ gamma,
                            const float* __restrict__ beta)
{
    __shared__ float red_s[8], red_t[8];
    const int n   = blockIdx.x;           // 0..63
    const int tid = threadIdx.x;          // 256
    const int k0  = tid * 8;

    float w[8], gv[8], bv[8];
    *(float4*)&w[0]  = *(const float4*)(w_down + n * HIDDEN + k0);
    *(float4*)&w[4]  = *(const float4*)(w_down + n * HIDDEN + k0 + 4);
    *(float4*)&gv[0] = *(const float4*)(gamma + k0);
    *(float4*)&gv[4] = *(const float4*)(gamma + k0 + 4);
    *(float4*)&bv[0] = *(const float4*)(beta + k0);
    *(float4*)&bv[4] = *(const float4*)(beta + k0 + 4);

    float ps = 0.f, pt = 0.f;
    uint32_t hw[4], lw[4];
    #pragma unroll
    for (int p = 0; p < 4; p++) {
        float g0 = gv[2*p] * w[2*p];
        float g1 = gv[2*p+1] * w[2*p+1];
        ps += g0 + g1;
        pt = fmaf(bv[2*p], w[2*p], pt);
        pt = fmaf(bv[2*p+1], w[2*p+1], pt);
        __nv_bfloat162 h = __floats2bfloat162_rn(g0, g1);
        float r0 = g0 - __bfloat162float(h.x);
        float r1 = g1 - __bfloat162float(h.y);
        __nv_bfloat162 l = __floats2bfloat162_rn(r0, r1);
        hw[p] = *(uint32_t*)&h;
        lw[p] = *(uint32_t*)&l;
    }
    {
        const int k16  = k0 >> 4;
        const int n8   = n >> 3;
        const int l0   = (n & 7) * 4;
        const int reg  = (k0 >> 3) & 1;
        const int base = ((k16 * 8 + n8) * 32 + l0) * 2 + reg;
        #pragma unroll
        for (int p = 0; p < 4; p++) {
            g_Bfh[base + p * 2] = hw[p];
            g_Bfl[base + p * 2] = lw[p];
        }
    }

    #pragma unroll
    for (int o = 16; o > 0; o >>= 1) {
        ps += __shfl_xor_sync(0xffffffffu, ps, o);
        pt += __shfl_xor_sync(0xffffffffu, pt, o);
    }
    int wi = tid >> 5, lane = tid & 31;
    if (lane == 0) { red_s[wi] = ps; red_t[wi] = pt; }
    __syncthreads();
    if (tid == 0) {
        float ss = 0.f, tt = 0.f;
        #pragma unroll
        for (int i = 0; i < 8; i++) { ss += red_s[i]; tt += red_t[i]; }
        g_s[n] = ss; g_t[n] = tt;
    }
}

// ---------------- main fused HMMA kernel ----------------------------------------
extern __shared__ char dsm[];

__global__ __launch_bounds__(THREADS, 2)
void router_kernel(const float* __restrict__ H,      // [16384][2048]
                   const float* __restrict__ w_up,   // [8][64]
                   float* __restrict__ out)          // [16384][8]
{
    const uint32_t sb  = smem_u32(dsm);
    const int tid  = threadIdx.x;
    const int wid  = tid >> 5;
    const int lane = tid & 31;
    const int pos  = wid & 3;             // warp position: 2m x 2n
    const int wm   = pos & 1;             // rows wm*32..+32
    const int wn   = pos >> 1;            // cols wn*32..+32
    const int kh   = wid >> 2;            // k-half within tile

    // small tables
    ((float*)(dsm + O_WUP))[tid]       = w_up[tid];
    ((float*)(dsm + O_WUP))[tid + 256] = w_up[tid + 256];
    if (tid < BOT) {
        ((float*)(dsm + O_S))[tid] = g_s[tid];
        ((float*)(dsm + O_T))[tid] = g_t[tid];
    }

    // A geometry: 4 float4/thread/tile; rows lrow+16j, k quad (tid&15)
    const int lrow = tid >> 4;
    const float* Hbase = H + ((size_t)blockIdx.x * BM + lrow) * HIDDEN + (tid & 15) * 4;
    const uint32_t sts_sw = SWZ128((uint32_t)(lrow * 128 + (tid & 15) * 8));

    const uint32_t half16 = (uint32_t)((lane >> 4) * 16);
    uint32_t aoff[2];
    #pragma unroll
    for (int mi = 0; mi < 2; mi++)
        aoff[mi] = SWZ128((uint32_t)((wm * 32 + mi * 16 + (lane & 15)) * 128)) ^ half16;

    const uint32_t bfbase = (uint32_t)(((kh * 2) * 8 + wn * 4) * 32 + lane) * 2;

    float acc[2][4][4];
    #pragma unroll
    for (int mi = 0; mi < 2; mi++)
        #pragma unroll
        for (int ni = 0; ni < 4; ni++)
            #pragma unroll
            for (int r = 0; r < 4; r++) acc[mi][ni][r] = 0.f;

    float psum[4] = {0.f, 0.f, 0.f, 0.f};
    float psq[4]  = {0.f, 0.f, 0.f, 0.f};
    float4 pf[4];
    uint2 bh2[2][4], bl2[2][4];

    // convert a register tile into A buffer cb (+ LN stats)
    auto convertTile = [&](const float4* v4, int cb) {
        #pragma unroll
        for (int j = 0; j < 4; j++) {
            float4 v = v4[j];
            psum[j] += (v.x + v.y) + (v.z + v.w);
            psq[j]  = fmaf(v.x, v.x, psq[j]); psq[j] = fmaf(v.y, v.y, psq[j]);
            psq[j]  = fmaf(v.z, v.z, psq[j]); psq[j] = fmaf(v.w, v.w, psq[j]);
            __nv_bfloat162 h01 = __floats2bfloat162_rn(v.x, v.y);
            __nv_bfloat162 h23 = __floats2bfloat162_rn(v.z, v.w);
            float rx = v.x - __bfloat162float(h01.x);
            float ry = v.y - __bfloat162float(h01.y);
            float rz = v.z - __bfloat162float(h23.x);
            float rw = v.w - __bfloat162float(h23.y);
            __nv_bfloat162 l01 = __floats2bfloat162_rn(rx, ry);
            __nv_bfloat162 l23 = __floats2bfloat162_rn(rz, rw);
            uint32_t sw = sts_sw + (uint32_t)(j * 2048);
            *(uint2*)(dsm + A_HI(cb) + sw) = make_uint2(*(uint32_t*)&h01, *(uint32_t*)&h23);
            *(uint2*)(dsm + A_LO(cb) + sw) = make_uint2(*(uint32_t*)&l01, *(uint32_t*)&l23);
        }
    };

    // ---- prologue: tiles 0,1 -> buffers 0,1; pf <- tile 2; B(0) -> regs ----
    {
        float4 pg[4];
        #pragma unroll
        for (int j = 0; j < 4; j++)
            pf[j] = *(const float4*)(Hbase + (size_t)j * 16 * HIDDEN);
        #pragma unroll
        for (int j = 0; j < 4; j++)
            pg[j] = *(const float4*)(Hbase + BK + (size_t)j * 16 * HIDDEN);
        convertTile(pf, 0);
        convertTile(pg, 1);
        #pragma unroll
        for (int j = 0; j < 4; j++)
            pf[j] = *(const float4*)(Hbase + 2 * BK + (size_t)j * 16 * HIDDEN);
    }
    #pragma unroll
    for (int ss = 0; ss < 2; ss++) {
        const uint32_t o = bfbase + (uint32_t)ss * 512;
        #pragma unroll
        for (int j = 0; j < 4; j++) {
            bh2[ss][j] = *(const uint2*)&g_Bfh[o + j * 64];
            bl2[ss][j] = *(const uint2*)&g_Bfl[o + j * 64];
        }
    }
    __syncthreads();            // tiles 0,1 + tables visible

    // ---- mainloop: barrier every 2 tiles (4-deep A pipeline) ----
    #pragma unroll 1
    for (int t = 0; t < NTILES; t++) {
        const int buf = t & 3;
        // MMA for tile t (B already in regs)
        {
            const uint32_t ab_hi = sb + A_HI(buf), ab_lo = sb + A_LO(buf);
            #pragma unroll
            for (int ss = 0; ss < 2; ss++) {
                const uint32_t ks = (uint32_t)(kh * 64 + ss * 32);
                uint32_t ah[2][4], al[2][4];
                #pragma unroll
                for (int mi = 0; mi < 2; mi++) {
                    LDMX4(ah[mi], ab_hi + (aoff[mi] ^ ks));
                    LDMX4(al[mi], ab_lo + (aoff[mi] ^ ks));
                }
                #pragma unroll
                for (int mi = 0; mi < 2; mi++)
                    #pragma unroll
                    for (int ni = 0; ni < 4; ni++) {
                        MMA16816(acc[mi][ni], ah[mi], bh2[ss][ni].x, bh2[ss][ni].y);
                        MMA16816(acc[mi][ni], ah[mi], bl2[ss][ni].x, bl2[ss][ni].y);
                        MMA16816(acc[mi][ni], al[mi], bh2[ss][ni].x, bh2[ss][ni].y);
                    }
            }
        }
        // load B fragments for tile t+1
        if (t + 1 < NTILES) {
            const uint32_t tb = bfbase + (uint32_t)(t + 1) * 2048;
            #pragma unroll
            for (int ss = 0; ss < 2; ss++) {
                const uint32_t o = tb + (uint32_t)ss * 512;
                #pragma unroll
                for (int j = 0; j < 4; j++) {
                    bh2[ss][j] = *(const uint2*)&g_Bfh[o + j * 64];
                    bl2[ss][j] = *(const uint2*)&g_Bfl[o + j * 64];
                }
            }
        }
        // convert tile t+2 (in pf) into buffer (t+2)&3
        if (t + 2 < NTILES)
            convertTile(pf, (t + 2) & 3);
        // prefetch tile t+3 into pf
        if (t + 3 < NTILES) {
            const float* hp = Hbase + (t + 3) * BK;
            #pragma unroll
            for (int j = 0; j < 4; j++)
                pf[j] = *(const float4*)(hp + (size_t)j * 16 * HIDDEN);
        }
        if (t & 1) __syncthreads();   // one barrier per 2 tiles (t=31 ends with one)
    }

    // ---- kh=1 warps dump k-partials ----
    if (kh == 1) {
        float* pp = (float*)(dsm + O_PART) + pos * 1024;
        #pragma unroll
        for (int mi = 0; mi < 2; mi++)
            #pragma unroll
            for (int ni = 0; ni < 4; ni++)
                #pragma unroll
                for (int r = 0; r < 4; r++)
                    pp[((mi * 4 + ni) * 4 + r) * 32 + lane] = acc[mi][ni][r];
    }
    // ---- LN stats ----
    #pragma unroll
    for (int o = 1; o < 16; o <<= 1) {
        #pragma unroll
        for (int j = 0; j < 4; j++) {
            psum[j] += __shfl_xor_sync(0xffffffffu, psum[j], o);
            psq[j]  += __shfl_xor_sync(0xffffffffu, psq[j], o);
        }
    }
    if ((tid & 15) == 0) {
        #pragma unroll
        for (int j = 0; j < 4; j++) {
            int row = j * 16 + lrow;
            float mu  = psum[j] * (1.f / HIDDEN);
            float var = psq[j] * (1.f / HIDDEN) - mu * mu;
            ((float*)(dsm + O_MU))[row] = mu;
            ((float*)(dsm + O_RS))[row] = rsqrtf(var + 1e-5f);
        }
    }
    __syncthreads();

    // ---- kh=0: merge partials, LN-correct + SiLU -> z ----
    if (kh == 0) {
        float* zb = (float*)(dsm + O_ZB);
        const float* pp  = (const float*)(dsm + O_PART) + pos * 1024;
        const float* muA = (const float*)(dsm + O_MU);
        const float* rsA = (const float*)(dsm + O_RS);
        const float* sA  = (const float*)(dsm + O_S);
        const float* tA  = (const float*)(dsm + O_T);
        #pragma unroll
        for (int mi = 0; mi < 2; mi++) {
            int r0 = wm * 32 + mi * 16 + (lane >> 2);
            float mu0 = muA[r0], rs0 = rsA[r0];
            float mu1 = muA[r0 + 8], rs1 = rsA[r0 + 8];
            #pragma unroll
            for (int ni = 0; ni < 4; ni++) {
                const float* pf4 = pp + ((mi * 4 + ni) * 4) * 32 + lane;
                float a0 = acc[mi][ni][0] + pf4[0];
                float a1 = acc[mi][ni][1] + pf4[32];
                float a2 = acc[mi][ni][2] + pf4[64];
                float a3 = acc[mi][ni][3] + pf4[96];
                int c0 = wn * 32 + ni * 8 + (lane & 3) * 2;
                float s0 = sA[c0], s1 = sA[c0 + 1];
                float t0 = tA[c0], t1 = tA[c0 + 1];
                float p00 = rs0 * (a0 - mu0 * s0) + t0;
                float p01 = rs0 * (a1 - mu0 * s1) + t1;
                float p10 = rs1 * (a2 - mu1 * s0) + t0;
                float p11 = rs1 * (a3 - mu1 * s1) + t1;
                float z00 = p00 / (1.f + __expf(-p00));
                float z01 = p01 / (1.f + __expf(-p01));
                float z10 = p10 / (1.f + __expf(-p10));
                float z11 = p11 / (1.f + __expf(-p11));
                *(float2*)&zb[r0 * ZSTRIDE + c0]       = make_float2(z00, z01);
                *(float2*)&zb[(r0 + 8) * ZSTRIDE + c0] = make_float2(z10, z11);
            }
        }
    }
    __syncthreads();

    // ---- router GEMM ----
    {
        const int m = tid & 63, eg = tid >> 6;
        const float* zr = (const float*)(dsm + O_ZB) + m * ZSTRIDE;
        const float* w0 = (const float*)(dsm + O_WUP) + eg * 128;
        const float* w1 = w0 + 64;
        float l0 = 0.f, l1 = 0.f;
        #pragma unroll
        for (int d4 = 0; d4 < 16; d4++) {
            float4 zv = ((const float4*)zr)[d4];
            float4 wa = ((const float4*)w0)[d4];
            float4 wb = ((const float4*)w1)[d4];
            l0 = fmaf(zv.x, wa.x, l0); l0 = fmaf(zv.y, wa.y, l0);
            l0 = fmaf(zv.z, wa.z, l0); l0 = fmaf(zv.w, wa.w, l0);
            l1 = fmaf(zv.x, wb.x, l1); l1 = fmaf(zv.y, wb.y, l1);
            l1 = fmaf(zv.z, wb.z, l1); l1 = fmaf(zv.w, wb.w, l1);
        }
        ((float*)(dsm + O_LG))[m * 8 + eg * 2]     = l0;
        ((float*)(dsm + O_LG))[m * 8 + eg * 2 + 1] = l1;
    }
    __syncthreads();

    // ---- top-2 softmax (first-index tie-break matches jax.lax.top_k) ----
    if (tid < BM) {
        const float* lp = (const float*)(dsm + O_LG) + tid * 8;
        float lg[8];
        #pragma unroll
        for (int e = 0; e < 8; e++) lg[e] = lp[e];
        int i1 = 0; float m1 = lg[0];
        #pragma unroll
        for (int e = 1; e < 8; e++) if (lg[e] > m1) { m1 = lg[e]; i1 = e; }
        int i2 = -1; float m2 = -3.4e38f;
        #pragma unroll
        for (int e = 0; e < 8; e++) if (e != i1 && lg[e] > m2) { m2 = lg[e]; i2 = e; }
        float p1 = 1.f / (1.f + __expf(m2 - m1));
        float p2 = 1.f - p1;
        float o[8];
        #pragma unroll
        for (int e = 0; e < 8; e++) o[e] = (e == i1) ? p1 : (e == i2) ? p2 : 0.f;
        float* op = out + ((size_t)blockIdx.x * BM + tid) * NEXP;
        *(float4*)op       = make_float4(o[0], o[1], o[2], o[3]);
        *(float4*)(op + 4) = make_float4(o[4], o[5], o[6], o[7]);
    }
}

// ---------------- launch --------------------------------------------------------
extern "C" void kernel_launch(void* const* d_in, const int* in_sizes, int n_in,
                              void* d_out, int out_size)
{
    (void)in_sizes; (void)n_in; (void)out_size;
    const float* hs     = (const float*)d_in[0];
    const float* w_down = (const float*)d_in[1];
    const float* w_up   = (const float*)d_in[2];
    const float* gamma  = (const float*)d_in[3];
    const float* beta   = (const float*)d_in[4];
    float* out = (float*)d_out;

    static int attr_done = 0;
    if (!attr_done) {
        cudaFuncSetAttribute(router_kernel, cudaFuncAttributeMaxDynamicSharedMemorySize, SMEM_TOTAL);
        attr_done = 1;
    }
    prep_kernel<<<BOT, THREADS>>>(w_down, gamma, beta);
    router_kernel<<<NBLK, THREADS, SMEM_TOTAL>>>(hs, w_up, out);
}

// round 17
// speedup vs baseline: 1.0385x; 1.0385x over previous
#include <cuda_runtime.h>
#include <cuda_bf16.h>
#include <math.h>
#include <stdint.h>

#define HIDDEN 2048
#define BOT    64
#define NEXP   8
#define NTOK   16384

#define BM       64
#define BK       64
#define NTILES   (HIDDEN / BK)       // 32
#define THREADS  256
#define NBLK     (NTOK / BM)         // 256

// ---------------- dynamic smem layout (byte offsets) ---------------------------
#define A_HI(b)   ((b) * 8192)                // 2 x 8KB (64 rows x 128B bf16)
#define A_LO(b)   (16384 + (b) * 8192)        // 2 x 8KB
#define O_PART    0                           // 16KB k-partials (reuses A_HI post-loop)
#define O_ZB      16384                       // 17408B z buffer [64][68] (reuses A_LO)
#define O_MU      33792                       // 64 f32
#define O_RS      34048
#define O_S       34304
#define O_T       34560
#define O_WUP     34816                       // 2KB raw w_up [8][64]
#define O_LG      36864                       // 2KB logits [64][8]
#define SMEM_TOTAL 38912
#define ZSTRIDE   68

#define SWZ128(off) ((off) ^ (((off) >> 3) & 0x70))

// ---------------- device scratch (no allocations allowed) ----------------------
// B in mma.sync fragment order: index = ((k16blk*8 + n8blk)*32 + lane)*2 + reg
__device__ uint32_t g_Bfh[128 * 8 * 32 * 2];   // 256KB hi fragments
__device__ uint32_t g_Bfl[128 * 8 * 32 * 2];   // 256KB lo fragments
__device__ float g_sp[4 * BOT];                // s partials per k-quarter
__device__ float g_tp[4 * BOT];                // t partials per k-quarter

// ---------------- PTX helpers ---------------------------------------------------
__device__ __forceinline__ uint32_t smem_u32(const void* p) {
    uint32_t a;
    asm("{ .reg .u64 t; cvta.to.shared.u64 t, %1; cvt.u32.u64 %0, t; }" : "=r"(a) : "l"(p));
    return a;
}
#define LDMX4(r, a) \
    asm volatile("ldmatrix.sync.aligned.m8n8.x4.shared.b16 {%0,%1,%2,%3}, [%4];" \
        : "=r"((r)[0]), "=r"((r)[1]), "=r"((r)[2]), "=r"((r)[3]) : "r"(a))

#define MMA16816(d, a, b0, b1) \
    asm volatile("mma.sync.aligned.m16n8k16.row.col.f32.bf16.bf16.f32 " \
        "{%0,%1,%2,%3}, {%4,%5,%6,%7}, {%8,%9}, {%0,%1,%2,%3};" \
        : "+f"((d)[0]), "+f"((d)[1]), "+f"((d)[2]), "+f"((d)[3]) \
        : "r"((a)[0]), "r"((a)[1]), "r"((a)[2]), "r"((a)[3]), "r"(b0), "r"(b1))

// ---------------- prep v2: 256 CTAs, one 512-k slice each -----------------------
__global__ void prep_kernel(const float* __restrict__ w_down,
                            const float* __restrict__ gamma,
                            const float* __restrict__ beta)
{
    __shared__ float red_s[8], red_t[8];
    const int n   = blockIdx.x;           // 0..63
    const int kq  = blockIdx.y;           // 0..3
    const int tid = threadIdx.x;          // 256
    const int k0  = kq * 512 + tid * 2;   // one k-pair per thread

    float2 w  = *(const float2*)(w_down + n * HIDDEN + k0);
    float2 gv = *(const float2*)(gamma + k0);
    float2 bv = *(const float2*)(beta + k0);

    float g0 = gv.x * w.x, g1 = gv.y * w.y;
    float ps = g0 + g1;
    float pt = fmaf(bv.x, w.x, bv.y * w.y);
    __nv_bfloat162 h = __floats2bfloat162_rn(g0, g1);
    __nv_bfloat162 l = __floats2bfloat162_rn(g0 - __bfloat162float(h.x),
                                             g1 - __bfloat162float(h.y));
    {
        const int k16  = k0 >> 4;
        const int n8   = n >> 3;
        const int reg  = (k0 >> 3) & 1;
        const int lpos = (n & 7) * 4 + ((k0 >> 1) & 3);
        const int idx  = ((k16 * 8 + n8) * 32 + lpos) * 2 + reg;
        g_Bfh[idx] = *(uint32_t*)&h;
        g_Bfl[idx] = *(uint32_t*)&l;
    }
    #pragma unroll
    for (int o = 16; o > 0; o >>= 1) {
        ps += __shfl_xor_sync(0xffffffffu, ps, o);
        pt += __shfl_xor_sync(0xffffffffu, pt, o);
    }
    const int wi = tid >> 5, lane = tid & 31;
    if (lane == 0) { red_s[wi] = ps; red_t[wi] = pt; }
    __syncthreads();
    if (tid == 0) {
        float ss = 0.f, tt = 0.f;
        #pragma unroll
        for (int i = 0; i < 8; i++) { ss += red_s[i]; tt += red_t[i]; }
        g_sp[kq * BOT + n] = ss;
        g_tp[kq * BOT + n] = tt;
    }
}

// ---------------- main fused HMMA kernel ----------------------------------------
extern __shared__ char dsm[];

__global__ __launch_bounds__(THREADS, 2)
void router_kernel(const float* __restrict__ H,      // [16384][2048]
                   const float* __restrict__ w_up,   // [8][64]
                   float* __restrict__ out)          // [16384][8]
{
    const uint32_t sb  = smem_u32(dsm);
    const int tid  = threadIdx.x;
    const int wid  = tid >> 5;
    const int lane = tid & 31;
    const int pos  = wid & 3;             // warp position: 2m x 2n
    const int wm   = pos & 1;             // rows wm*32..+32
    const int wn   = pos >> 1;            // cols wn*32..+32
    const int kh   = wid >> 2;            // k-half within tile

    // small tables (s/t summed from prep partials)
    ((float*)(dsm + O_WUP))[tid]       = w_up[tid];
    ((float*)(dsm + O_WUP))[tid + 256] = w_up[tid + 256];
    if (tid < BOT) {
        ((float*)(dsm + O_S))[tid] = g_sp[tid] + g_sp[64 + tid] + g_sp[128 + tid] + g_sp[192 + tid];
        ((float*)(dsm + O_T))[tid] = g_tp[tid] + g_tp[64 + tid] + g_tp[128 + tid] + g_tp[192 + tid];
    }

    // A geometry: 4 float4/thread/tile; rows lrow+16j, k quad (tid&15)
    const int lrow = tid >> 4;
    const float* Hbase = H + ((size_t)blockIdx.x * BM + lrow) * HIDDEN + (tid & 15) * 4;
    const uint32_t sts_sw = SWZ128((uint32_t)(lrow * 128 + (tid & 15) * 8));

    const uint32_t half16 = (uint32_t)((lane >> 4) * 16);
    uint32_t aoff[2];
    #pragma unroll
    for (int mi = 0; mi < 2; mi++)
        aoff[mi] = SWZ128((uint32_t)((wm * 32 + mi * 16 + (lane & 15)) * 128)) ^ half16;

    const uint32_t bfbase = (uint32_t)(((kh * 2) * 8 + wn * 4) * 32 + lane) * 2;

    float acc[2][4][4];
    #pragma unroll
    for (int mi = 0; mi < 2; mi++)
        #pragma unroll
        for (int ni = 0; ni < 4; ni++)
            #pragma unroll
            for (int r = 0; r < 4; r++) acc[mi][ni][r] = 0.f;

    float psum[4] = {0.f, 0.f, 0.f, 0.f};
    float psq[4]  = {0.f, 0.f, 0.f, 0.f};
    float4 pf[4];
    uint2 bh2[2][4], bl2[2][4];          // B fragments, pipelined one tile ahead

    // ---- prologue: A0 -> regs -> convert -> smem(0); A1 -> pf; B(0) -> regs ----
    #pragma unroll
    for (int j = 0; j < 4; j++)
        pf[j] = *(const float4*)(Hbase + (size_t)j * 16 * HIDDEN);
    #pragma unroll
    for (int j = 0; j < 4; j++) {
        float4 v = pf[j];
        psum[j] += (v.x + v.y) + (v.z + v.w);
        psq[j]  = fmaf(v.x, v.x, psq[j]); psq[j] = fmaf(v.y, v.y, psq[j]);
        psq[j]  = fmaf(v.z, v.z, psq[j]); psq[j] = fmaf(v.w, v.w, psq[j]);
        __nv_bfloat162 h01 = __floats2bfloat162_rn(v.x, v.y);
        __nv_bfloat162 h23 = __floats2bfloat162_rn(v.z, v.w);
        float rx = v.x - __bfloat162float(h01.x);
        float ry = v.y - __bfloat162float(h01.y);
        float rz = v.z - __bfloat162float(h23.x);
        float rw = v.w - __bfloat162float(h23.y);
        __nv_bfloat162 l01 = __floats2bfloat162_rn(rx, ry);
        __nv_bfloat162 l23 = __floats2bfloat162_rn(rz, rw);
        uint32_t sw = sts_sw + (uint32_t)(j * 2048);
        *(uint2*)(dsm + A_HI(0) + sw) = make_uint2(*(uint32_t*)&h01, *(uint32_t*)&h23);
        *(uint2*)(dsm + A_LO(0) + sw) = make_uint2(*(uint32_t*)&l01, *(uint32_t*)&l23);
    }
    #pragma unroll
    for (int j = 0; j < 4; j++)
        pf[j] = *(const float4*)(Hbase + BK + (size_t)j * 16 * HIDDEN);
    #pragma unroll
    for (int ss = 0; ss < 2; ss++) {
        const uint32_t o = bfbase + (uint32_t)ss * 512;
        #pragma unroll
        for (int j = 0; j < 4; j++) {
            bh2[ss][j] = *(const uint2*)&g_Bfh[o + j * 64];
            bl2[ss][j] = *(const uint2*)&g_Bfl[o + j * 64];
        }
    }
    __syncthreads();            // tile 0 A + tables visible

    #pragma unroll 1
    for (int t = 0; t < NTILES; t++) {
        const int buf = t & 1, nb = buf ^ 1;
        // ---- MMA phase for tile t (pass-major: same-acc MMAs 8 apart) ----
        {
            const uint32_t ab_hi = sb + A_HI(buf), ab_lo = sb + A_LO(buf);
            #pragma unroll
            for (int ss = 0; ss < 2; ss++) {
                const uint32_t ks = (uint32_t)(kh * 64 + ss * 32);
                uint32_t ah[2][4], al[2][4];
                #pragma unroll
                for (int mi = 0; mi < 2; mi++) {
                    LDMX4(ah[mi], ab_hi + (aoff[mi] ^ ks));
                    LDMX4(al[mi], ab_lo + (aoff[mi] ^ ks));
                }
                #pragma unroll
                for (int mi = 0; mi < 2; mi++)
                    #pragma unroll
                    for (int ni = 0; ni < 4; ni++)
                        MMA16816(acc[mi][ni], ah[mi], bh2[ss][ni].x, bh2[ss][ni].y);
                #pragma unroll
                for (int mi = 0; mi < 2; mi++)
                    #pragma unroll
                    for (int ni = 0; ni < 4; ni++)
                        MMA16816(acc[mi][ni], ah[mi], bl2[ss][ni].x, bl2[ss][ni].y);
                #pragma unroll
                for (int mi = 0; mi < 2; mi++)
                    #pragma unroll
                    for (int ni = 0; ni < 4; ni++)
                        MMA16816(acc[mi][ni], al[mi], bh2[ss][ni].x, bh2[ss][ni].y);
            }
        }
        // ---- load B fragments for tile t+1 (pre-barrier latency cover) ----
        if (t + 1 < NTILES) {
            const uint32_t tb = bfbase + (uint32_t)(t + 1) * 2048;
            #pragma unroll
            for (int ss = 0; ss < 2; ss++) {
                const uint32_t o = tb + (uint32_t)ss * 512;
                #pragma unroll
                for (int j = 0; j < 4; j++) {
                    bh2[ss][j] = *(const uint2*)&g_Bfh[o + j * 64];
                    bl2[ss][j] = *(const uint2*)&g_Bfl[o + j * 64];
                }
            }
        }
        // ---- convert A_{t+1} -> nb (overlaps tensor work of tile t) ----
        if (t + 1 < NTILES) {
            #pragma unroll
            for (int j = 0; j < 4; j++) {
                float4 v = pf[j];
                psum[j] += (v.x + v.y) + (v.z + v.w);
                psq[j]  = fmaf(v.x, v.x, psq[j]); psq[j] = fmaf(v.y, v.y, psq[j]);
                psq[j]  = fmaf(v.z, v.z, psq[j]); psq[j] = fmaf(v.w, v.w, psq[j]);
                __nv_bfloat162 h01 = __floats2bfloat162_rn(v.x, v.y);
                __nv_bfloat162 h23 = __floats2bfloat162_rn(v.z, v.w);
                float rx = v.x - __bfloat162float(h01.x);
                float ry = v.y - __bfloat162float(h01.y);
                float rz = v.z - __bfloat162float(h23.x);
                float rw = v.w - __bfloat162float(h23.y);
                __nv_bfloat162 l01 = __floats2bfloat162_rn(rx, ry);
                __nv_bfloat162 l23 = __floats2bfloat162_rn(rz, rw);
                uint32_t sw = sts_sw + (uint32_t)(j * 2048);
                *(uint2*)(dsm + A_HI(nb) + sw) = make_uint2(*(uint32_t*)&h01, *(uint32_t*)&h23);
                *(uint2*)(dsm + A_LO(nb) + sw) = make_uint2(*(uint32_t*)&l01, *(uint32_t*)&l23);
            }
        }
        // ---- prefetch A_{t+2} f32 ----
        if (t + 2 < NTILES) {
            const float* hp = Hbase + (t + 2) * BK;
            #pragma unroll
            for (int j = 0; j < 4; j++)
                pf[j] = *(const float4*)(hp + (size_t)j * 16 * HIDDEN);
        }
        __syncthreads();
    }

    // ---- kh=1 warps dump k-partials ----
    if (kh == 1) {
        float* pp = (float*)(dsm + O_PART) + pos * 1024;
        #pragma unroll
        for (int mi = 0; mi < 2; mi++)
            #pragma unroll
            for (int ni = 0; ni < 4; ni++)
                #pragma unroll
                for (int r = 0; r < 4; r++)
                    pp[((mi * 4 + ni) * 4 + r) * 32 + lane] = acc[mi][ni][r];
    }
    // ---- LN stats ----
    #pragma unroll
    for (int o = 1; o < 16; o <<= 1) {
        #pragma unroll
        for (int j = 0; j < 4; j++) {
            psum[j] += __shfl_xor_sync(0xffffffffu, psum[j], o);
            psq[j]  += __shfl_xor_sync(0xffffffffu, psq[j], o);
        }
    }
    if ((tid & 15) == 0) {
        #pragma unroll
        for (int j = 0; j < 4; j++) {
            int row = j * 16 + lrow;
            float mu  = psum[j] * (1.f / HIDDEN);
            float var = psq[j] * (1.f / HIDDEN) - mu * mu;
            ((float*)(dsm + O_MU))[row] = mu;
            ((float*)(dsm + O_RS))[row] = rsqrtf(var + 1e-5f);
        }
    }
    __syncthreads();

    // ---- kh=0: merge partials, LN-correct + SiLU -> z ----
    if (kh == 0) {
        float* zb = (float*)(dsm + O_ZB);
        const float* pp  = (const float*)(dsm + O_PART) + pos * 1024;
        const float* muA = (const float*)(dsm + O_MU);
        const float* rsA = (const float*)(dsm + O_RS);
        const float* sA  = (const float*)(dsm + O_S);
        const float* tA  = (const float*)(dsm + O_T);
        #pragma unroll
        for (int mi = 0; mi < 2; mi++) {
            int r0 = wm * 32 + mi * 16 + (lane >> 2);
            float mu0 = muA[r0], rs0 = rsA[r0];
            float mu1 = muA[r0 + 8], rs1 = rsA[r0 + 8];
            #pragma unroll
            for (int ni = 0; ni < 4; ni++) {
                const float* pf4 = pp + ((mi * 4 + ni) * 4) * 32 + lane;
                float a0 = acc[mi][ni][0] + pf4[0];
                float a1 = acc[mi][ni][1] + pf4[32];
                float a2 = acc[mi][ni][2] + pf4[64];
                float a3 = acc[mi][ni][3] + pf4[96];
                int c0 = wn * 32 + ni * 8 + (lane & 3) * 2;
                float s0 = sA[c0], s1 = sA[c0 + 1];
                float t0 = tA[c0], t1 = tA[c0 + 1];
                float p00 = rs0 * (a0 - mu0 * s0) + t0;
                float p01 = rs0 * (a1 - mu0 * s1) + t1;
                float p10 = rs1 * (a2 - mu1 * s0) + t0;
                float p11 = rs1 * (a3 - mu1 * s1) + t1;
                float z00 = p00 / (1.f + __expf(-p00));
                float z01 = p01 / (1.f + __expf(-p01));
                float z10 = p10 / (1.f + __expf(-p10));
                float z11 = p11 / (1.f + __expf(-p11));
                *(float2*)&zb[r0 * ZSTRIDE + c0]       = make_float2(z00, z01);
                *(float2*)&zb[(r0 + 8) * ZSTRIDE + c0] = make_float2(z10, z11);
            }
        }
    }
    __syncthreads();

    // ---- router GEMM ----
    {
        const int m = tid & 63, eg = tid >> 6;
        const float* zr = (const float*)(dsm + O_ZB) + m * ZSTRIDE;
        const float* w0 = (const float*)(dsm + O_WUP) + eg * 128;
        const float* w1 = w0 + 64;
        float l0 = 0.f, l1 = 0.f;
        #pragma unroll
        for (int d4 = 0; d4 < 16; d4++) {
            float4 zv = ((const float4*)zr)[d4];
            float4 wa = ((const float4*)w0)[d4];
            float4 wb = ((const float4*)w1)[d4];
            l0 = fmaf(zv.x, wa.x, l0); l0 = fmaf(zv.y, wa.y, l0);
            l0 = fmaf(zv.z, wa.z, l0); l0 = fmaf(zv.w, wa.w, l0);
            l1 = fmaf(zv.x, wb.x, l1); l1 = fmaf(zv.y, wb.y, l1);
            l1 = fmaf(zv.z, wb.z, l1); l1 = fmaf(zv.w, wb.w, l1);
        }
        ((float*)(dsm + O_LG))[m * 8 + eg * 2]     = l0;
        ((float*)(dsm + O_LG))[m * 8 + eg * 2 + 1] = l1;
    }
    __syncthreads();

    // ---- top-2 softmax (first-index tie-break matches jax.lax.top_k) ----
    if (tid < BM) {
        const float* lp = (const float*)(dsm + O_LG) + tid * 8;
        float lg[8];
        #pragma unroll
        for (int e = 0; e < 8; e++) lg[e] = lp[e];
        int i1 = 0; float m1 = lg[0];
        #pragma unroll
        for (int e = 1; e < 8; e++) if (lg[e] > m1) { m1 = lg[e]; i1 = e; }
        int i2 = -1; float m2 = -3.4e38f;
        #pragma unroll
        for (int e = 0; e < 8; e++) if (e != i1 && lg[e] > m2) { m2 = lg[e]; i2 = e; }
        float p1 = 1.f / (1.f + __expf(m2 - m1));
        float p2 = 1.f - p1;
        float o[8];
        #pragma unroll
        for (int e = 0; e < 8; e++) o[e] = (e == i1) ? p1 : (e == i2) ? p2 : 0.f;
        float* op = out + ((size_t)blockIdx.x * BM + tid) * NEXP;
        *(float4*)op       = make_float4(o[0], o[1], o[2], o[3]);
        *(float4*)(op + 4) = make_float4(o[4], o[5], o[6], o[7]);
    }
}

// ---------------- launch --------------------------------------------------------
extern "C" void kernel_launch(void* const* d_in, const int* in_sizes, int n_in,
                              void* d_out, int out_size)
{
    (void)in_sizes; (void)n_in; (void)out_size;
    const float* hs     = (const float*)d_in[0];
    const float* w_down = (const float*)d_in[1];
    const float* w_up   = (const float*)d_in[2];
    const float* gamma  = (const float*)d_in[3];
    const float* beta   = (const float*)d_in[4];
    float* out = (float*)d_out;

    static int attr_done = 0;
    if (!attr_done) {
        cudaFuncSetAttribute(router_kernel, cudaFuncAttributeMaxDynamicSharedMemorySize, SMEM_TOTAL);
        attr_done = 1;
    }
    prep_kernel<<<dim3(BOT, 4), THREADS>>>(w_down, gamma, beta);
    router_kernel<<<NBLK, THREADS, SMEM_TOTAL>>>(hs, w_up, out);
}